// round 4
// baseline (speedup 1.0000x reference)
#include <cuda_runtime.h>
#include <cuda_bf16.h>
#include <math.h>

#define BB 8192
#define FF 24
#define VV 100000
#define DD 64
#define PP 276  // FF*(FF-1)/2

// Scratch (allocation-free rule: __device__ globals)
__device__ uint2 g_wpk[PP];  // {bf16x2 splat wMul, bf16x2 splat wD}
__device__ float g_cA[FF];   // per-field coefficient for the s_plus term

// ---------------------------------------------------------------------------
// Prep: fold arch_w (+flag semantics) into bf16x2 pair weights + fp32 cA.
//   t_p = wS*s_plus + wMul*s_mul + wD*s_absdiff
//   wS = w0 + w4 + 0.5*(w2+w3);  wMul = w1;  wD = 0.5*(w2-w3)
//   flag==0 == flag==1 with one-hot(argmax) weights.
// ---------------------------------------------------------------------------
__global__ void ofm_prep_kernel(const float* __restrict__ arch_w,
                                const int* __restrict__ flagp) {
    int t = threadIdx.x;
    if (t < FF) g_cA[t] = 0.0f;
    __syncthreads();
    if (t < PP) {
        int i = 1, p = t;
        while (p >= i) { p -= i; i++; }
        int j = p;

        float w[5];
#pragma unroll
        for (int k = 0; k < 5; k++) w[k] = arch_w[t * 5 + k];

        if (*flagp == 0) {
            int sel = 0;
            float best = w[0];
#pragma unroll
            for (int k = 1; k < 5; k++)
                if (w[k] > best) { best = w[k]; sel = k; }
#pragma unroll
            for (int k = 0; k < 5; k++) w[k] = (k == sel) ? 1.0f : 0.0f;
        }

        float wS = w[0] + w[4] + 0.5f * (w[2] + w[3]);
        float wD = 0.5f * (w[2] - w[3]);

        __nv_bfloat162 m2 = __float2bfloat162_rn(w[1]);
        __nv_bfloat162 d2 = __float2bfloat162_rn(wD);
        g_wpk[t] = make_uint2(*reinterpret_cast<unsigned*>(&m2),
                              *reinterpret_cast<unsigned*>(&d2));
        atomicAdd(&g_cA[i], wS);
        atomicAdd(&g_cA[j], wS);
    }
}

// ---------------------------------------------------------------------------
// Main kernel: one warp per TWO batch rows; each lane owns 2 of the 64 dims
// as one bf16x2 register per row. Per pair: one broadcast LDS.64 weight
// fetch shared by both rows + 2x(HMUL2,HFMA2,HSUB2,HFMA2) on the fma pipe +
// 2 integer-AND abs on the alu pipe. Four independent accumulator chains.
// bf16x2 partials flushed to fp32 per i-row (<=23 adds) for error bounds.
// ---------------------------------------------------------------------------
__global__ __launch_bounds__(256, 3) void ofm_main_kernel(
    const int* __restrict__ x,
    const float* __restrict__ emb2,
    const float* __restrict__ emb1,
    const float* __restrict__ bias,
    float* __restrict__ out) {

    __shared__ uint2 s_w[PP];
    __shared__ float s_cA[FF];

    int tid = threadIdx.x;
    for (int k = tid; k < PP; k += 256)
        s_w[k] = g_wpk[k];
    if (tid < FF) s_cA[tid] = g_cA[tid];
    __syncthreads();

    int warp = tid >> 5;
    int lane = tid & 31;
    int row0 = (blockIdx.x * 8 + warp) * 2;  // BB % 16 == 0
    int row1 = row0 + 1;

    // Gather x indices + emb1 values (lanes 0..23), both rows
    int xv0 = 0, xv1 = 0;
    float e1v0 = 0.0f, e1v1 = 0.0f;
    if (lane < FF) {
        xv0 = x[row0 * FF + lane];
        xv1 = x[row1 * FF + lane];
        e1v0 = emb1[(size_t)lane * VV + xv0];
        e1v1 = emb1[(size_t)lane * VV + xv1];
    }

    // Gather e2 tiles (fp32, 256B coalesced per field), fold fp32 s_plus,
    // keep bf16x2 copies for the pair loop.
    __nv_bfloat162 eb0[FF], eb1[FF];
    float splus0 = (lane < FF) ? e1v0 : 0.0f;
    float splus1 = (lane < FF) ? e1v1 : 0.0f;
#pragma unroll
    for (int f = 0; f < FF; f++) {
        int xf0 = __shfl_sync(0xffffffffu, xv0, f);
        int xf1 = __shfl_sync(0xffffffffu, xv1, f);
        const float2* p0 =
            reinterpret_cast<const float2*>(emb2 + ((size_t)f * VV + xf0) * DD) + lane;
        const float2* p1 =
            reinterpret_cast<const float2*>(emb2 + ((size_t)f * VV + xf1) * DD) + lane;
        float2 v0 = __ldg(p0);
        float2 v1 = __ldg(p1);
        splus0 = fmaf(s_cA[f], v0.x + v0.y, splus0);
        splus1 = fmaf(s_cA[f], v1.x + v1.y, splus1);
        eb0[f] = __float22bfloat162_rn(v0);
        eb1[f] = __float22bfloat162_rn(v1);
    }

    float accM0 = 0.0f, accA0 = 0.0f, accM1 = 0.0f, accA1 = 0.0f;

#pragma unroll
    for (int i = 1; i < FF; i++) {
        unsigned aM0 = 0u, aA0 = 0u, aM1 = 0u, aA1 = 0u;  // bf16x2 accums
#pragma unroll
        for (int j = 0; j < i; j++) {
            const int p = i * (i - 1) / 2 + j;
            uint2 wraw = s_w[p];  // one broadcast LDS.64 for both rows
            __nv_bfloat162 wm = *reinterpret_cast<__nv_bfloat162*>(&wraw.x);
            __nv_bfloat162 wd = *reinterpret_cast<__nv_bfloat162*>(&wraw.y);

            // row 0
            {
                __nv_bfloat162 prod = __hmul2(eb0[i], eb0[j]);
                __nv_bfloat162 am = *reinterpret_cast<__nv_bfloat162*>(&aM0);
                am = __hfma2(wm, prod, am);
                aM0 = *reinterpret_cast<unsigned*>(&am);

                __nv_bfloat162 dif = __hsub2(eb0[i], eb0[j]);
                unsigned ud = *reinterpret_cast<unsigned*>(&dif) & 0x7FFF7FFFu;
                __nv_bfloat162 ad = *reinterpret_cast<__nv_bfloat162*>(&ud);
                __nv_bfloat162 aa = *reinterpret_cast<__nv_bfloat162*>(&aA0);
                aa = __hfma2(wd, ad, aa);
                aA0 = *reinterpret_cast<unsigned*>(&aa);
            }
            // row 1
            {
                __nv_bfloat162 prod = __hmul2(eb1[i], eb1[j]);
                __nv_bfloat162 am = *reinterpret_cast<__nv_bfloat162*>(&aM1);
                am = __hfma2(wm, prod, am);
                aM1 = *reinterpret_cast<unsigned*>(&am);

                __nv_bfloat162 dif = __hsub2(eb1[i], eb1[j]);
                unsigned ud = *reinterpret_cast<unsigned*>(&dif) & 0x7FFF7FFFu;
                __nv_bfloat162 ad = *reinterpret_cast<__nv_bfloat162*>(&ud);
                __nv_bfloat162 aa = *reinterpret_cast<__nv_bfloat162*>(&aA1);
                aa = __hfma2(wd, ad, aa);
                aA1 = *reinterpret_cast<unsigned*>(&aa);
            }
        }
        // Flush bf16x2 chunk partials to fp32 (shift/mask on alu pipe)
        accM0 += __uint_as_float(aM0 << 16) + __uint_as_float(aM0 & 0xFFFF0000u);
        accA0 += __uint_as_float(aA0 << 16) + __uint_as_float(aA0 & 0xFFFF0000u);
        accM1 += __uint_as_float(aM1 << 16) + __uint_as_float(aM1 & 0xFFFF0000u);
        accA1 += __uint_as_float(aA1 << 16) + __uint_as_float(aA1 & 0xFFFF0000u);
    }

    float acc0 = splus0 + accM0 + accA0;
    float acc1 = splus1 + accM1 + accA1;

    // Warp reductions (cover all 64 dims + e1 partials)
#pragma unroll
    for (int o = 16; o; o >>= 1) {
        acc0 += __shfl_xor_sync(0xffffffffu, acc0, o);
        acc1 += __shfl_xor_sync(0xffffffffu, acc1, o);
    }

    if (lane == 0) {
        float z0 = acc0 + bias[0];
        float z1 = acc1 + bias[0];
        out[row0] = 1.0f / (1.0f + expf(-z0));
        out[row1] = 1.0f / (1.0f + expf(-z1));
    }
}

// ---------------------------------------------------------------------------
// d_in order: 0=x(int32 B*F), 1=flag(int32), 2=emb2(f32 F*V*D),
//             3=emb1(f32 F*V), 4=bias(f32 1), 5=arch_w(f32 P*5)
// ---------------------------------------------------------------------------
extern "C" void kernel_launch(void* const* d_in, const int* in_sizes, int n_in,
                              void* d_out, int out_size) {
    const int* x = (const int*)d_in[0];
    const int* flag = (const int*)d_in[1];
    const float* emb2 = (const float*)d_in[2];
    const float* emb1 = (const float*)d_in[3];
    const float* bias = (const float*)d_in[4];
    const float* arch_w = (const float*)d_in[5];
    float* out = (float*)d_out;

    ofm_prep_kernel<<<1, 288>>>(arch_w, flag);
    ofm_main_kernel<<<BB / 16, 256>>>(x, emb2, emb1, bias, out);
}